// round 8
// baseline (speedup 1.0000x reference)
#include <cuda_runtime.h>
#include <cuda_fp16.h>
#include <cuda_bf16.h>

// LightGCN: CSR SpMM x3, fp16 feature buffers, fp32 row accumulation.
// Round 8 (resubmit of R7 after infra failure): degree-grouped row
// scheduling. Rows are permuted by degree (counting sort, <=1024 bins) so
// each warp's 4 row-groups have equal length -> no intra-warp divergence
// waste (~25% of iterations before). Degree histogram is fused into the
// CSR scan; perm build uses block-aggregated bucket atomics.

constexpr int NUSERS = 100000;
constexpr int NITEMS = 50000;
constexpr int NNODES = 150000;
constexpr int NNZ_E  = 4800000;
constexpr int HVEC   = NNODES * 8;    // uint4 (8 halves) per fp16 buffer
constexpr int DBINS  = 1024;          // degree bins (clamped)

constexpr int TB          = 256;
constexpr int SCAN_NBLK   = (NNODES + TB - 1) / TB;      // 586
constexpr int EDGE_BLOCKS = (NNZ_E + TB - 1) / TB;       // 18750
constexpr int HVEC_BLOCKS = (HVEC + TB - 1) / TB;        // 4688

// ---- scratch ----
struct ZeroRegion {                    // zeroed with ONE cudaMemsetAsync
    int cnt[NNODES];
    unsigned long long state[SCAN_NBLK];
    unsigned int ticket;
    int dhist[DBINS];
    int dtick[DBINS];
};
__device__ ZeroRegion g_zs;
__device__ uint4 g_h0[HVEC];
__device__ uint4 g_h1[HVEC];
__device__ uint4 g_h2[HVEC];
__device__ int   g_rowptr[NNODES + 1];
__device__ int   g_rowcur[NNODES];
__device__ int   g_perm[NNODES];       // rows sorted by degree
__device__ int2  g_meta[NNZ_E];        // {dst, val bits} sorted by src

// ---------------- CSR build ----------------

__global__ void hist_kernel(const int4* __restrict__ src4) {
    int t = blockIdx.x * blockDim.x + threadIdx.x;
    if (t < NNZ_E / 4) {
        int4 s = __ldg(&src4[t]);
        atomicAdd(&g_zs.cnt[s.x], 1);
        atomicAdd(&g_zs.cnt[s.y], 1);
        atomicAdd(&g_zs.cnt[s.z], 1);
        atomicAdd(&g_zs.cnt[s.w], 1);
    }
}

// Single-pass exclusive scan with decoupled lookback + fused degree histogram.
__global__ void scan_onepass() {
    __shared__ int s[TB];
    __shared__ int sdh[DBINS];
    __shared__ int sbid;
    __shared__ int sprefix;
    int tid = threadIdx.x;
    if (tid == 0) {
        sbid = (int)atomicAdd(&g_zs.ticket, 1u);
        sprefix = 0;
    }
    for (int b = tid; b < DBINS; b += TB) sdh[b] = 0;
    __syncthreads();
    int bid = sbid;
    int i = bid * TB + tid;
    int v = (i < NNODES) ? g_zs.cnt[i] : 0;
    if (i < NNODES) atomicAdd(&sdh[min(v, DBINS - 1)], 1);
    s[tid] = v;
    __syncthreads();
    #pragma unroll
    for (int off = 1; off < TB; off <<= 1) {
        int x = (tid >= off) ? s[tid - off] : 0;
        __syncthreads();
        s[tid] += x;
        __syncthreads();
    }
    int incl  = s[tid];
    int total = s[TB - 1];

    // flush block-local degree histogram
    for (int b = tid; b < DBINS; b += TB)
        if (sdh[b]) atomicAdd(&g_zs.dhist[b], sdh[b]);

    if (tid == 0) {
        unsigned long long pkt =
            ((unsigned long long)((bid == 0) ? 2u : 1u) << 32) | (unsigned int)total;
        atomicExch(&g_zs.state[bid], pkt);
    }

    if (bid > 0 && tid < 32) {
        int look = bid - 1;
        int pfx = 0;
        for (;;) {
            int j = look - tid;
            int flag, val;
            if (j >= 0) {
                unsigned long long pkt;
                do {
                    pkt = atomicAdd(&g_zs.state[j], 0ULL);
                    flag = (int)(pkt >> 32);
                } while (flag == 0);
                val = (int)(unsigned int)pkt;
            } else { flag = 2; val = 0; }
            unsigned int ball = __ballot_sync(0xffffffffu, flag == 2);
            int first = __ffs(ball) - 1;
            int contrib = (first < 0) ? val : ((tid <= first) ? val : 0);
            #pragma unroll
            for (int o = 16; o; o >>= 1)
                contrib += __shfl_down_sync(0xffffffffu, contrib, o);
            if (tid == 0) pfx += contrib;
            if (ball) break;
            look -= 32;
        }
        if (tid == 0) {
            sprefix = pfx;
            atomicExch(&g_zs.state[bid],
                       ((unsigned long long)2u << 32) | (unsigned int)(total + pfx));
        }
    }
    __syncthreads();
    int excl = sprefix + incl - v;
    if (i < NNODES) {
        g_rowptr[i] = excl;
        g_rowcur[i] = excl;
    }
    if (i == NNODES - 1) g_rowptr[NNODES] = NNZ_E;
}

// Build degree-sorted row permutation.
// Every block redundantly scans the (small) degree histogram in smem, then
// rows claim positions via block-aggregated bucket atomics.
__global__ void perm_build() {
    __shared__ int soff[DBINS];   // exclusive global start of each bin
    __shared__ int scnt[DBINS];   // block-local count per bin
    __shared__ int sbase[DBINS];  // global base within bin for this block
    __shared__ int bs[TB];
    int tid = threadIdx.x;

    // exclusive scan of dhist (4 bins per thread + block scan of partials)
    int d0 = tid * 4;
    int h0 = g_zs.dhist[d0], h1 = g_zs.dhist[d0 + 1];
    int h2 = g_zs.dhist[d0 + 2], h3 = g_zs.dhist[d0 + 3];
    int lsum = h0 + h1 + h2 + h3;
    bs[tid] = lsum;
    __syncthreads();
    #pragma unroll
    for (int off = 1; off < TB; off <<= 1) {
        int x = (tid >= off) ? bs[tid - off] : 0;
        __syncthreads();
        bs[tid] += x;
        __syncthreads();
    }
    int excl = bs[tid] - lsum;
    soff[d0]     = excl;
    soff[d0 + 1] = excl + h0;
    soff[d0 + 2] = excl + h0 + h1;
    soff[d0 + 3] = excl + h0 + h1 + h2;
    scnt[d0] = 0; scnt[d0 + 1] = 0; scnt[d0 + 2] = 0; scnt[d0 + 3] = 0;
    __syncthreads();

    // phase 1: local ranks
    int i = blockIdx.x * TB + tid;
    int d = -1, lr = 0;
    if (i < NNODES) {
        d = min(g_zs.cnt[i], DBINS - 1);
        lr = atomicAdd(&scnt[d], 1);
    }
    __syncthreads();
    // phase 2: one global reservation per nonzero bin
    for (int b = tid; b < DBINS; b += TB)
        if (scnt[b]) sbase[b] = atomicAdd(&g_zs.dtick[b], scnt[b]);
    __syncthreads();
    if (i < NNODES)
        g_perm[soff[d] + sbase[d] + lr] = i;
}

// scatter (first EDGE_BLOCKS blocks) fused with init h0 (rest).
__global__ void scatter_init_kernel(const int*    __restrict__ src,
                                    const int*    __restrict__ dst,
                                    const float*  __restrict__ val,
                                    const float4* __restrict__ user,
                                    const float4* __restrict__ item) {
    if (blockIdx.x < EDGE_BLOCKS) {
        int e = blockIdx.x * TB + threadIdx.x;
        if (e < NNZ_E) {
            int sN = __ldg(&src[e]);
            int pos = atomicAdd(&g_rowcur[sN], 1);
            g_meta[pos] = make_int2(__ldg(&dst[e]), __float_as_int(__ldg(&val[e])));
        }
    } else {
        int i = (blockIdx.x - EDGE_BLOCKS) * TB + threadIdx.x;
        if (i < HVEC) {
            int j = i * 2;
            float4 a = (j     < NUSERS * 16) ? __ldg(&user[j])     : __ldg(&item[j - NUSERS * 16]);
            float4 b = (j + 1 < NUSERS * 16) ? __ldg(&user[j + 1]) : __ldg(&item[j + 1 - NUSERS * 16]);
            union { uint4 u; __half2 h[4]; } o;
            o.h[0] = __floats2half2_rn(a.x, a.y);
            o.h[1] = __floats2half2_rn(a.z, a.w);
            o.h[2] = __floats2half2_rn(b.x, b.y);
            o.h[3] = __floats2half2_rn(b.z, b.w);
            g_h0[i] = o.u;
        }
    }
}

// ---------------- SpMM core: 8 lanes/row, 8 floats/lane ----------------

struct Acc8 { float v[8]; };

__device__ __forceinline__ void fma8(Acc8& a, float w, uint4 u) {
    union { uint4 u; __half2 h[4]; } x;
    x.u = u;
    #pragma unroll
    for (int k = 0; k < 4; k++) {
        float2 f = __half22float2(x.h[k]);
        a.v[2*k]   += w * f.x;
        a.v[2*k+1] += w * f.y;
    }
}

__device__ __forceinline__ Acc8 spmm_row(const uint4* __restrict__ in,
                                         int row, int lane) {
    int beg = __ldg(&g_rowptr[row]);
    int end = __ldg(&g_rowptr[row + 1]);
    Acc8 acc;
    #pragma unroll
    for (int k = 0; k < 8; k++) acc.v[k] = 0.f;
    int i = beg;
    for (; i + 4 <= end; i += 4) {
        int2 m0 = __ldg(&g_meta[i]);
        int2 m1 = __ldg(&g_meta[i + 1]);
        int2 m2 = __ldg(&g_meta[i + 2]);
        int2 m3 = __ldg(&g_meta[i + 3]);
        uint4 x0 = __ldg(&in[m0.x * 8 + lane]);
        uint4 x1 = __ldg(&in[m1.x * 8 + lane]);
        uint4 x2 = __ldg(&in[m2.x * 8 + lane]);
        uint4 x3 = __ldg(&in[m3.x * 8 + lane]);
        fma8(acc, __int_as_float(m0.y), x0);
        fma8(acc, __int_as_float(m1.y), x1);
        fma8(acc, __int_as_float(m2.y), x2);
        fma8(acc, __int_as_float(m3.y), x3);
    }
    for (; i < end; i++) {
        int2 m = __ldg(&g_meta[i]);
        uint4 x = __ldg(&in[m.x * 8 + lane]);
        fma8(acc, __int_as_float(m.y), x);
    }
    return acc;
}

// Layers 1,2: out_h = fp16(A * in), rows in degree-sorted order
__global__ void spmm_kernel(const uint4* __restrict__ in,
                            uint4*       __restrict__ out_h) {
    int gtid = blockIdx.x * blockDim.x + threadIdx.x;
    int idx  = gtid >> 3;
    int lane = gtid & 7;
    if (idx >= NNODES) return;
    int row = __ldg(&g_perm[idx]);

    Acc8 s = spmm_row(in, row, lane);

    union { uint4 u; __half2 h[4]; } o;
    o.h[0] = __floats2half2_rn(s.v[0], s.v[1]);
    o.h[1] = __floats2half2_rn(s.v[2], s.v[3]);
    o.h[2] = __floats2half2_rn(s.v[4], s.v[5]);
    o.h[3] = __floats2half2_rn(s.v[6], s.v[7]);
    out_h[row * 8 + lane] = o.u;
}

// Layer 3 + epilogue: out = 0.25 * (h0 + h1 + h2 + A*h2)
__global__ void spmm_final_kernel(float4* __restrict__ out) {
    int gtid = blockIdx.x * blockDim.x + threadIdx.x;
    int idx  = gtid >> 3;
    int lane = gtid & 7;
    if (idx >= NNODES) return;
    int row = __ldg(&g_perm[idx]);

    Acc8 s = spmm_row(g_h2, row, lane);

    int hidx = row * 8 + lane;
    union { uint4 u; __half2 h[4]; } a, b, c;
    a.u = g_h0[hidx];
    b.u = g_h1[hidx];
    c.u = g_h2[hidx];

    float r[8];
    #pragma unroll
    for (int k = 0; k < 4; k++) {
        float2 fa = __half22float2(a.h[k]);
        float2 fb = __half22float2(b.h[k]);
        float2 fc = __half22float2(c.h[k]);
        r[2*k]   = 0.25f * (fa.x + fb.x + fc.x + s.v[2*k]);
        r[2*k+1] = 0.25f * (fa.y + fb.y + fc.y + s.v[2*k+1]);
    }
    int o0 = row * 16 + lane * 2;
    out[o0]     = make_float4(r[0], r[1], r[2], r[3]);
    out[o0 + 1] = make_float4(r[4], r[5], r[6], r[7]);
}

// ---------------- launch ----------------

extern "C" void kernel_launch(void* const* d_in, const int* in_sizes, int n_in,
                              void* d_out, int out_size) {
    const float4* user = (const float4*)d_in[0];
    const float4* item = (const float4*)d_in[1];
    const int*    esrc = (const int*)d_in[2];
    const int*    edst = (const int*)d_in[3];
    const float*  eval = (const float*)d_in[4];
    float4* out = (float4*)d_out;

    uint4 *h0, *h1, *h2;
    void* zs;
    cudaGetSymbolAddress((void**)&h0, g_h0);
    cudaGetSymbolAddress((void**)&h1, g_h1);
    cudaGetSymbolAddress((void**)&h2, g_h2);
    cudaGetSymbolAddress(&zs, g_zs);

    cudaMemsetAsync(zs, 0, sizeof(ZeroRegion));

    hist_kernel<<<(NNZ_E / 4 + TB - 1) / TB, TB>>>((const int4*)esrc);
    scan_onepass<<<SCAN_NBLK, TB>>>();
    perm_build<<<SCAN_NBLK, TB>>>();
    scatter_init_kernel<<<EDGE_BLOCKS + HVEC_BLOCKS, TB>>>(esrc, edst, eval, user, item);

    spmm_kernel<<<HVEC_BLOCKS, TB>>>(h0, h1);
    spmm_kernel<<<HVEC_BLOCKS, TB>>>(h1, h2);
    spmm_final_kernel<<<HVEC_BLOCKS, TB>>>(out);
}